// round 1
// baseline (speedup 1.0000x reference)
#include <cuda_runtime.h>
#include <math.h>

#define NHEAD   8
#define HD      64
#define D_MODEL 512
#define B_SZ    2
#define SEQ     4096

// Scratch (allocation-free rule: __device__ globals)
__device__ float g_q [B_SZ*SEQ*D_MODEL];
__device__ float g_k [B_SZ*SEQ*D_MODEL];
__device__ float g_v [B_SZ*SEQ*D_MODEL];
__device__ float g_ao[B_SZ*SEQ*D_MODEL];

// ---------------------------------------------------------------------------
// GEMM: C[M,N] = A[M,K] @ W[K,N] + bias[N]   (all row-major fp32)
// 128x128 block tile, BK=8, 256 threads, 8x8 register tile per thread.
// ---------------------------------------------------------------------------
__global__ __launch_bounds__(256) void gemm_bias_kernel(
    const float* __restrict__ A, const float* __restrict__ W,
    const float* __restrict__ bias, float* __restrict__ C,
    int M, int N, int K)
{
    __shared__ float As[8][128];   // [k][m]
    __shared__ float Bs[8][128];   // [k][n]

    const int tid  = threadIdx.x;
    const int tx   = tid & 15;
    const int ty   = tid >> 4;
    const int row0 = blockIdx.y * 128;
    const int col0 = blockIdx.x * 128;

    float acc[8][8];
#pragma unroll
    for (int i = 0; i < 8; i++)
#pragma unroll
        for (int j = 0; j < 8; j++) acc[i][j] = 0.f;

    const int ar = tid >> 1;          // 0..127 row within A tile
    const int ak = (tid & 1) << 2;    // 0 or 4
    const int bk = tid >> 5;          // 0..7
    const int bc = (tid & 31) << 2;   // 0..124

    for (int k0 = 0; k0 < K; k0 += 8) {
        float4 av = *(const float4*)(A + (size_t)(row0 + ar) * K + k0 + ak);
        As[ak + 0][ar] = av.x;
        As[ak + 1][ar] = av.y;
        As[ak + 2][ar] = av.z;
        As[ak + 3][ar] = av.w;
        *(float4*)&Bs[bk][bc] =
            *(const float4*)(W + (size_t)(k0 + bk) * N + col0 + bc);
        __syncthreads();

#pragma unroll
        for (int kk = 0; kk < 8; kk++) {
            float a[8], b[8];
            *(float4*)&a[0] = *(const float4*)&As[kk][ty * 8];
            *(float4*)&a[4] = *(const float4*)&As[kk][ty * 8 + 4];
            *(float4*)&b[0] = *(const float4*)&Bs[kk][tx * 8];
            *(float4*)&b[4] = *(const float4*)&Bs[kk][tx * 8 + 4];
#pragma unroll
            for (int i = 0; i < 8; i++)
#pragma unroll
                for (int j = 0; j < 8; j++)
                    acc[i][j] += a[i] * b[j];
        }
        __syncthreads();
    }

#pragma unroll
    for (int i = 0; i < 8; i++) {
        float* crow = C + (size_t)(row0 + ty * 8 + i) * N + col0 + tx * 8;
#pragma unroll
        for (int j0 = 0; j0 < 8; j0 += 4) {
            float4 o;
            o.x = acc[i][j0 + 0] + bias[col0 + tx * 8 + j0 + 0];
            o.y = acc[i][j0 + 1] + bias[col0 + tx * 8 + j0 + 1];
            o.z = acc[i][j0 + 2] + bias[col0 + tx * 8 + j0 + 2];
            o.w = acc[i][j0 + 3] + bias[col0 + tx * 8 + j0 + 3];
            *(float4*)(crow + j0) = o;
        }
    }
}

// ---------------------------------------------------------------------------
// Flash attention, fp32. One block per (b, h, 64-query tile).
// 256 threads as 16x16, each owns 4x4 subtiles of the 64x64 S and O tiles.
// Online softmax: row stats reduced over the 16-lane row-group via shfl_xor.
// Layouts in smem (stride 68 floats keeps float4 alignment + bank spread):
//   Qs[d][q], Ks[d][k]  (transposed -> contiguous float4 reads in d-loop)
//   Vs[k][d]            (direct copy)
//   Ps[k][q]            (P stored transposed -> contiguous float4 in k-loop)
// ---------------------------------------------------------------------------
#define QT 64
#define KT 64
#define SP 68
#define ATTN_SMEM (4 * HD * SP * (int)sizeof(float))   // 69632 B

__global__ __launch_bounds__(256) void attn_kernel(
    const float* __restrict__ Q, const float* __restrict__ Kg,
    const float* __restrict__ Vg, float* __restrict__ O)
{
    extern __shared__ float sm[];
    float* Qs = sm;
    float* Ks = sm + HD * SP;
    float* Vs = sm + 2 * HD * SP;
    float* Ps = sm + 3 * HD * SP;

    const int bh = blockIdx.y;
    const int b  = bh >> 3;
    const int h  = bh & 7;
    const int q0 = blockIdx.x * QT;

    const int tid = threadIdx.x;
    const int tx  = tid & 15;
    const int ty  = tid >> 4;

    const float* Qbase = Q  + (size_t)b * SEQ * D_MODEL + h * HD;
    const float* Kbase = Kg + (size_t)b * SEQ * D_MODEL + h * HD;
    const float* Vbase = Vg + (size_t)b * SEQ * D_MODEL + h * HD;

    // Load Q tile transposed: Qs[d][q]
    {
        const int qr = tid >> 2;
        const int d0 = (tid & 3) * 16;
        const float* src = Qbase + (size_t)(q0 + qr) * D_MODEL + d0;
#pragma unroll
        for (int u = 0; u < 4; u++) {
            float4 v = *(const float4*)(src + u * 4);
            int d = d0 + u * 4;
            Qs[(d + 0) * SP + qr] = v.x;
            Qs[(d + 1) * SP + qr] = v.y;
            Qs[(d + 2) * SP + qr] = v.z;
            Qs[(d + 3) * SP + qr] = v.w;
        }
    }

    float acc[4][4];
#pragma unroll
    for (int i = 0; i < 4; i++)
#pragma unroll
        for (int j = 0; j < 4; j++) acc[i][j] = 0.f;

    float mrow[4], lrow[4];
#pragma unroll
    for (int i = 0; i < 4; i++) { mrow[i] = -1e30f; lrow[i] = 0.f; }

    for (int kt = 0; kt < SEQ; kt += KT) {
        // Load K tile transposed (Ks[d][k]) and V tile direct (Vs[k][d])
        {
            const int kr = tid >> 2;
            const int d0 = (tid & 3) * 16;
            const float* ksrc = Kbase + (size_t)(kt + kr) * D_MODEL + d0;
            const float* vsrc = Vbase + (size_t)(kt + kr) * D_MODEL + d0;
#pragma unroll
            for (int u = 0; u < 4; u++) {
                float4 kv = *(const float4*)(ksrc + u * 4);
                int d = d0 + u * 4;
                Ks[(d + 0) * SP + kr] = kv.x;
                Ks[(d + 1) * SP + kr] = kv.y;
                Ks[(d + 2) * SP + kr] = kv.z;
                Ks[(d + 3) * SP + kr] = kv.w;
                float4 vv = *(const float4*)(vsrc + u * 4);
                *(float4*)&Vs[kr * SP + d] = vv;
            }
        }
        __syncthreads();

        // S = (Q K^T) * 1/sqrt(Hd)
        float s[4][4];
#pragma unroll
        for (int i = 0; i < 4; i++)
#pragma unroll
            for (int j = 0; j < 4; j++) s[i][j] = 0.f;

#pragma unroll 16
        for (int d = 0; d < HD; d++) {
            float4 a = *(const float4*)&Qs[d * SP + ty * 4];
            float4 bb = *(const float4*)&Ks[d * SP + tx * 4];
            float av[4] = {a.x, a.y, a.z, a.w};
            float bv[4] = {bb.x, bb.y, bb.z, bb.w};
#pragma unroll
            for (int i = 0; i < 4; i++)
#pragma unroll
                for (int j = 0; j < 4; j++)
                    s[i][j] += av[i] * bv[j];
        }
#pragma unroll
        for (int i = 0; i < 4; i++)
#pragma unroll
            for (int j = 0; j < 4; j++) s[i][j] *= 0.125f;

        // Online softmax per row (row-group = 16 contiguous lanes, same ty)
#pragma unroll
        for (int i = 0; i < 4; i++) {
            float rm = fmaxf(fmaxf(s[i][0], s[i][1]), fmaxf(s[i][2], s[i][3]));
#pragma unroll
            for (int off = 8; off >= 1; off >>= 1)
                rm = fmaxf(rm, __shfl_xor_sync(0xffffffffu, rm, off, 16));
            float nm = fmaxf(mrow[i], rm);
            float p0 = __expf(s[i][0] - nm);
            float p1 = __expf(s[i][1] - nm);
            float p2 = __expf(s[i][2] - nm);
            float p3 = __expf(s[i][3] - nm);
            float rs = (p0 + p1) + (p2 + p3);
#pragma unroll
            for (int off = 8; off >= 1; off >>= 1)
                rs += __shfl_xor_sync(0xffffffffu, rs, off, 16);
            float sc = __expf(mrow[i] - nm);
            lrow[i] = lrow[i] * sc + rs;
            mrow[i] = nm;
#pragma unroll
            for (int j = 0; j < 4; j++) acc[i][j] *= sc;
            s[i][0] = p0; s[i][1] = p1; s[i][2] = p2; s[i][3] = p3;
        }

        // Store P transposed: Ps[k][q]
#pragma unroll
        for (int j = 0; j < 4; j++)
#pragma unroll
            for (int i = 0; i < 4; i++)
                Ps[(tx * 4 + j) * SP + ty * 4 + i] = s[i][j];
        __syncthreads();

        // O += P V
#pragma unroll 16
        for (int k = 0; k < KT; k++) {
            float4 a = *(const float4*)&Ps[k * SP + ty * 4];
            float4 bb = *(const float4*)&Vs[k * SP + tx * 4];
            float av[4] = {a.x, a.y, a.z, a.w};
            float bv[4] = {bb.x, bb.y, bb.z, bb.w};
#pragma unroll
            for (int i = 0; i < 4; i++)
#pragma unroll
                for (int j = 0; j < 4; j++)
                    acc[i][j] += av[i] * bv[j];
        }
        __syncthreads();
    }

    // Normalize + write O[b, q0+row, h, d]
    float* Obase = O + (size_t)(b * SEQ + q0) * D_MODEL + h * HD;
#pragma unroll
    for (int i = 0; i < 4; i++) {
        float inv = 1.0f / lrow[i];
        float4 o;
        o.x = acc[i][0] * inv;
        o.y = acc[i][1] * inv;
        o.z = acc[i][2] * inv;
        o.w = acc[i][3] * inv;
        *(float4*)(Obase + (size_t)(ty * 4 + i) * D_MODEL + tx * 4) = o;
    }
}

// ---------------------------------------------------------------------------
extern "C" void kernel_launch(void* const* d_in, const int* in_sizes, int n_in,
                              void* d_out, int out_size)
{
    const float* x  = (const float*)d_in[0];
    const float* Wq = (const float*)d_in[1];
    const float* bq = (const float*)d_in[2];
    const float* Wk = (const float*)d_in[3];
    const float* bk = (const float*)d_in[4];
    const float* Wv = (const float*)d_in[5];
    const float* bv = (const float*)d_in[6];
    const float* Wo = (const float*)d_in[7];
    const float* bo = (const float*)d_in[8];
    float* out = (float*)d_out;

    float *q, *k, *v, *ao;
    cudaGetSymbolAddress((void**)&q,  g_q);
    cudaGetSymbolAddress((void**)&k,  g_k);
    cudaGetSymbolAddress((void**)&v,  g_v);
    cudaGetSymbolAddress((void**)&ao, g_ao);

    cudaFuncSetAttribute(attn_kernel,
                         cudaFuncAttributeMaxDynamicSharedMemorySize, ATTN_SMEM);

    const int M = B_SZ * SEQ;
    dim3 ggrid(D_MODEL / 128, M / 128);

    gemm_bias_kernel<<<ggrid, 256>>>(x, Wq, bq, q, M, D_MODEL, D_MODEL);
    gemm_bias_kernel<<<ggrid, 256>>>(x, Wk, bk, k, M, D_MODEL, D_MODEL);
    gemm_bias_kernel<<<ggrid, 256>>>(x, Wv, bv, v, M, D_MODEL, D_MODEL);

    attn_kernel<<<dim3(SEQ / QT, B_SZ * NHEAD), 256, ATTN_SMEM>>>(q, k, v, ao);

    gemm_bias_kernel<<<ggrid, 256>>>(ao, Wo, bo, out, M, D_MODEL, D_MODEL);
}

// round 2
// speedup vs baseline: 1.4973x; 1.4973x over previous
#include <cuda_runtime.h>
#include <math.h>
#include <stdint.h>

#define NHEAD   8
#define HD      64
#define D_MODEL 512
#define B_SZ    2
#define SEQ     4096

// Scratch (allocation-free rule: __device__ globals)
__device__ float g_q [B_SZ*SEQ*D_MODEL];
__device__ float g_k [B_SZ*SEQ*D_MODEL];
__device__ float g_v [B_SZ*SEQ*D_MODEL];
__device__ float g_ao[B_SZ*SEQ*D_MODEL];

// ---------------------------------------------------------------------------
// GEMM: C[M,N] = A[M,K] @ W[K,N] + bias[N]   (all row-major fp32)
// 128x128 block tile, BK=8, 256 threads, 8x8 register tile per thread.
// (unchanged from round 1 — known good; tensor-core port is next round)
// ---------------------------------------------------------------------------
__global__ __launch_bounds__(256) void gemm_bias_kernel(
    const float* __restrict__ A, const float* __restrict__ W,
    const float* __restrict__ bias, float* __restrict__ C,
    int M, int N, int K)
{
    __shared__ float As[8][128];   // [k][m]
    __shared__ float Bs[8][128];   // [k][n]

    const int tid  = threadIdx.x;
    const int tx   = tid & 15;
    const int ty   = tid >> 4;
    const int row0 = blockIdx.y * 128;
    const int col0 = blockIdx.x * 128;

    float acc[8][8];
#pragma unroll
    for (int i = 0; i < 8; i++)
#pragma unroll
        for (int j = 0; j < 8; j++) acc[i][j] = 0.f;

    const int ar = tid >> 1;
    const int ak = (tid & 1) << 2;
    const int bk = tid >> 5;
    const int bc = (tid & 31) << 2;

    for (int k0 = 0; k0 < K; k0 += 8) {
        float4 av = *(const float4*)(A + (size_t)(row0 + ar) * K + k0 + ak);
        As[ak + 0][ar] = av.x;
        As[ak + 1][ar] = av.y;
        As[ak + 2][ar] = av.z;
        As[ak + 3][ar] = av.w;
        *(float4*)&Bs[bk][bc] =
            *(const float4*)(W + (size_t)(k0 + bk) * N + col0 + bc);
        __syncthreads();

#pragma unroll
        for (int kk = 0; kk < 8; kk++) {
            float a[8], b[8];
            *(float4*)&a[0] = *(const float4*)&As[kk][ty * 8];
            *(float4*)&a[4] = *(const float4*)&As[kk][ty * 8 + 4];
            *(float4*)&b[0] = *(const float4*)&Bs[kk][tx * 8];
            *(float4*)&b[4] = *(const float4*)&Bs[kk][tx * 8 + 4];
#pragma unroll
            for (int i = 0; i < 8; i++)
#pragma unroll
                for (int j = 0; j < 8; j++)
                    acc[i][j] += a[i] * b[j];
        }
        __syncthreads();
    }

#pragma unroll
    for (int i = 0; i < 8; i++) {
        float* crow = C + (size_t)(row0 + ty * 8 + i) * N + col0 + tx * 8;
#pragma unroll
        for (int j0 = 0; j0 < 8; j0 += 4) {
            float4 o;
            o.x = acc[i][j0 + 0] + bias[col0 + tx * 8 + j0 + 0];
            o.y = acc[i][j0 + 1] + bias[col0 + tx * 8 + j0 + 1];
            o.z = acc[i][j0 + 2] + bias[col0 + tx * 8 + j0 + 2];
            o.w = acc[i][j0 + 3] + bias[col0 + tx * 8 + j0 + 3];
            *(float4*)(crow + j0) = o;
        }
    }
}

// ---------------------------------------------------------------------------
// Flash attention v2: mma.sync m16n8k8 TF32 (HMMA on tensor pipe).
// Block = 8 warps = 128 query rows; 64-key tiles; HD = 64.
// Q kept in registers as split-TF32 fragments (hi+lo) for the whole k-loop.
// QK^T uses 3-term split TF32 (effectively fp32-accurate scores).
// PV uses single TF32 (P in [0,1], error ~3e-4).
// Smem strides: K/P stride 68 (frag reads conflict-free: banks 4g+t),
//               V stride 72 (frag reads conflict-free: banks 8t+g).
// ---------------------------------------------------------------------------
#define QT   128
#define KT   64
#define KSS  68
#define VSS  72
#define PSS  68
#define SM_KH 0
#define SM_KL (KT*KSS)                 // 4352 words
#define SM_V  (2*KT*KSS)               // 8704
#define SM_P  (2*KT*KSS + KT*VSS)      // 13312
#define SM_WORDS (SM_P + QT*PSS)       // 22016 words
#define ATTN_SMEM (SM_WORDS * 4)       // 88064 bytes

__device__ __forceinline__ uint32_t f2tf(float f) {
    uint32_t r;
    asm("cvt.rna.tf32.f32 %0, %1;" : "=r"(r) : "f"(f));
    return r;
}

__device__ __forceinline__ void mma8(float* c, const uint32_t* a,
                                     uint32_t b0, uint32_t b1) {
    asm volatile(
        "mma.sync.aligned.m16n8k8.row.col.f32.tf32.tf32.f32 "
        "{%0,%1,%2,%3}, {%4,%5,%6,%7}, {%8,%9}, {%0,%1,%2,%3};\n"
        : "+f"(c[0]), "+f"(c[1]), "+f"(c[2]), "+f"(c[3])
        : "r"(a[0]), "r"(a[1]), "r"(a[2]), "r"(a[3]), "r"(b0), "r"(b1));
}

__global__ __launch_bounds__(256) void attn_kernel(
    const float* __restrict__ Q, const float* __restrict__ Kg,
    const float* __restrict__ Vg, float* __restrict__ O)
{
    extern __shared__ uint32_t sm[];
    uint32_t* Kh = sm + SM_KH;
    uint32_t* Kl = sm + SM_KL;
    uint32_t* Vt = sm + SM_V;
    uint32_t* Ps = sm + SM_P;

    const int tid  = threadIdx.x;
    const int lane = tid & 31;
    const int warp = tid >> 5;
    const int g    = lane >> 2;   // groupID
    const int t    = lane & 3;    // threadID_in_group

    const int bh = blockIdx.y;
    const int b  = bh >> 3;
    const int h  = bh & 7;
    const int q0 = blockIdx.x * QT;

    const float* Qb = Q  + (size_t)b * SEQ * D_MODEL + h * HD;
    const float* Kb = Kg + (size_t)b * SEQ * D_MODEL + h * HD;
    const float* Vb = Vg + (size_t)b * SEQ * D_MODEL + h * HD;

    // --- stage Q: hi parts into Ps region, lo parts into Kh/Kl region ---
    for (int i = tid; i < QT * 16; i += 256) {
        int r = i >> 4;
        int c = (i & 15) * 4;
        float4 v = *(const float4*)(Qb + (size_t)(q0 + r) * D_MODEL + c);
        uint32_t h0 = f2tf(v.x), h1 = f2tf(v.y), h2 = f2tf(v.z), h3 = f2tf(v.w);
        *(uint4*)&Ps[r * PSS + c] = make_uint4(h0, h1, h2, h3);
        uint32_t l0 = f2tf(v.x - __uint_as_float(h0));
        uint32_t l1 = f2tf(v.y - __uint_as_float(h1));
        uint32_t l2 = f2tf(v.z - __uint_as_float(h2));
        uint32_t l3 = f2tf(v.w - __uint_as_float(h3));
        *(uint4*)&sm[r * 68 + c] = make_uint4(l0, l1, l2, l3);
    }
    __syncthreads();

    // --- load Q fragments into registers (A layout for m16n8k8 tf32) ---
    uint32_t qh[8][4], ql[8][4];
    const int rb = warp * 16 + g;
#pragma unroll
    for (int s = 0; s < 8; s++) {
        qh[s][0] = Ps[rb * PSS + 8 * s + t];
        qh[s][1] = Ps[(rb + 8) * PSS + 8 * s + t];
        qh[s][2] = Ps[rb * PSS + 8 * s + t + 4];
        qh[s][3] = Ps[(rb + 8) * PSS + 8 * s + t + 4];
        ql[s][0] = sm[rb * 68 + 8 * s + t];
        ql[s][1] = sm[(rb + 8) * 68 + 8 * s + t];
        ql[s][2] = sm[rb * 68 + 8 * s + t + 4];
        ql[s][3] = sm[(rb + 8) * 68 + 8 * s + t + 4];
    }
    __syncthreads();

    float o[8][4];
#pragma unroll
    for (int j = 0; j < 8; j++)
#pragma unroll
        for (int k4 = 0; k4 < 4; k4++) o[j][k4] = 0.f;
    float m0 = -1e30f, m1 = -1e30f, l0s = 0.f, l1s = 0.f;

    for (int kt = 0; kt < SEQ; kt += KT) {
        // --- stage K (split tf32) and V (tf32) tiles ---
        for (int i = tid; i < KT * 16; i += 256) {
            int r = i >> 4;
            int c = (i & 15) * 4;
            float4 kv = *(const float4*)(Kb + (size_t)(kt + r) * D_MODEL + c);
            uint32_t h0 = f2tf(kv.x), h1 = f2tf(kv.y), h2 = f2tf(kv.z), h3 = f2tf(kv.w);
            *(uint4*)&Kh[r * KSS + c] = make_uint4(h0, h1, h2, h3);
            *(uint4*)&Kl[r * KSS + c] = make_uint4(
                f2tf(kv.x - __uint_as_float(h0)),
                f2tf(kv.y - __uint_as_float(h1)),
                f2tf(kv.z - __uint_as_float(h2)),
                f2tf(kv.w - __uint_as_float(h3)));
            float4 vv = *(const float4*)(Vb + (size_t)(kt + r) * D_MODEL + c);
            *(uint4*)&Vt[r * VSS + c] =
                make_uint4(f2tf(vv.x), f2tf(vv.y), f2tf(vv.z), f2tf(vv.w));
        }
        __syncthreads();

        // --- S = Q K^T (split tf32: hi*hi + hi*lo + lo*hi) ---
        float sf[8][4];
#pragma unroll
        for (int j = 0; j < 8; j++)
#pragma unroll
            for (int k4 = 0; k4 < 4; k4++) sf[j][k4] = 0.f;

#pragma unroll
        for (int s = 0; s < 8; s++) {
#pragma unroll
            for (int j = 0; j < 8; j++) {
                int ko = (8 * j + g) * KSS + 8 * s + t;
                uint32_t bh0 = Kh[ko], bh1 = Kh[ko + 4];
                uint32_t bl0 = Kl[ko], bl1 = Kl[ko + 4];
                mma8(sf[j], qh[s], bh0, bh1);
                mma8(sf[j], qh[s], bl0, bl1);
                mma8(sf[j], ql[s], bh0, bh1);
            }
        }

        // --- online softmax (rows g and g+8 of this warp's 16-row tile) ---
        float rm0 = -1e30f, rm1 = -1e30f;
#pragma unroll
        for (int j = 0; j < 8; j++) {
            sf[j][0] *= 0.125f; sf[j][1] *= 0.125f;
            sf[j][2] *= 0.125f; sf[j][3] *= 0.125f;
            rm0 = fmaxf(rm0, fmaxf(sf[j][0], sf[j][1]));
            rm1 = fmaxf(rm1, fmaxf(sf[j][2], sf[j][3]));
        }
        rm0 = fmaxf(rm0, __shfl_xor_sync(0xffffffffu, rm0, 1));
        rm0 = fmaxf(rm0, __shfl_xor_sync(0xffffffffu, rm0, 2));
        rm1 = fmaxf(rm1, __shfl_xor_sync(0xffffffffu, rm1, 1));
        rm1 = fmaxf(rm1, __shfl_xor_sync(0xffffffffu, rm1, 2));

        float nm0 = fmaxf(m0, rm0), nm1 = fmaxf(m1, rm1);
        float f0 = __expf(m0 - nm0), f1 = __expf(m1 - nm1);

        float rs0 = 0.f, rs1 = 0.f;
        const int pb0 = (warp * 16 + g) * PSS;
#pragma unroll
        for (int j = 0; j < 8; j++) {
            float p0 = __expf(sf[j][0] - nm0);
            float p1 = __expf(sf[j][1] - nm0);
            float p2 = __expf(sf[j][2] - nm1);
            float p3 = __expf(sf[j][3] - nm1);
            rs0 += p0 + p1;
            rs1 += p2 + p3;
            int c = 8 * j + 2 * t;
            *(uint2*)&Ps[pb0 + c]           = make_uint2(f2tf(p0), f2tf(p1));
            *(uint2*)&Ps[pb0 + 8 * PSS + c] = make_uint2(f2tf(p2), f2tf(p3));
        }
        rs0 += __shfl_xor_sync(0xffffffffu, rs0, 1);
        rs0 += __shfl_xor_sync(0xffffffffu, rs0, 2);
        rs1 += __shfl_xor_sync(0xffffffffu, rs1, 1);
        rs1 += __shfl_xor_sync(0xffffffffu, rs1, 2);

        l0s = l0s * f0 + rs0;
        l1s = l1s * f1 + rs1;
        m0 = nm0; m1 = nm1;
#pragma unroll
        for (int j = 0; j < 8; j++) {
            o[j][0] *= f0; o[j][1] *= f0;
            o[j][2] *= f1; o[j][3] *= f1;
        }
        __syncwarp();

        // --- O += P V ---
#pragma unroll
        for (int s = 0; s < 8; s++) {
            uint32_t a[4];
            int pb = pb0 + 8 * s + t;
            a[0] = Ps[pb];
            a[1] = Ps[pb + 8 * PSS];
            a[2] = Ps[pb + 4];
            a[3] = Ps[pb + 8 * PSS + 4];
#pragma unroll
            for (int j = 0; j < 8; j++) {
                int vo = (8 * s + t) * VSS + 8 * j + g;
                mma8(o[j], a, Vt[vo], Vt[vo + 4 * VSS]);
            }
        }
        __syncthreads();
    }

    // --- normalize + write ---
    float i0 = 1.f / l0s, i1 = 1.f / l1s;
    float* Ob = O + (size_t)b * SEQ * D_MODEL + h * HD;
    const int r0 = q0 + warp * 16 + g;
    const int r1 = r0 + 8;
#pragma unroll
    for (int j = 0; j < 8; j++) {
        int d = 8 * j + 2 * t;
        *(float2*)(Ob + (size_t)r0 * D_MODEL + d) =
            make_float2(o[j][0] * i0, o[j][1] * i0);
        *(float2*)(Ob + (size_t)r1 * D_MODEL + d) =
            make_float2(o[j][2] * i1, o[j][3] * i1);
    }
}

// ---------------------------------------------------------------------------
extern "C" void kernel_launch(void* const* d_in, const int* in_sizes, int n_in,
                              void* d_out, int out_size)
{
    const float* x  = (const float*)d_in[0];
    const float* Wq = (const float*)d_in[1];
    const float* bq = (const float*)d_in[2];
    const float* Wk = (const float*)d_in[3];
    const float* bk = (const float*)d_in[4];
    const float* Wv = (const float*)d_in[5];
    const float* bv = (const float*)d_in[6];
    const float* Wo = (const float*)d_in[7];
    const float* bo = (const float*)d_in[8];
    float* out = (float*)d_out;

    float *q, *k, *v, *ao;
    cudaGetSymbolAddress((void**)&q,  g_q);
    cudaGetSymbolAddress((void**)&k,  g_k);
    cudaGetSymbolAddress((void**)&v,  g_v);
    cudaGetSymbolAddress((void**)&ao, g_ao);

    cudaFuncSetAttribute(attn_kernel,
                         cudaFuncAttributeMaxDynamicSharedMemorySize, ATTN_SMEM);

    const int M = B_SZ * SEQ;
    dim3 ggrid(D_MODEL / 128, M / 128);

    gemm_bias_kernel<<<ggrid, 256>>>(x, Wq, bq, q, M, D_MODEL, D_MODEL);
    gemm_bias_kernel<<<ggrid, 256>>>(x, Wk, bk, k, M, D_MODEL, D_MODEL);
    gemm_bias_kernel<<<ggrid, 256>>>(x, Wv, bv, v, M, D_MODEL, D_MODEL);

    attn_kernel<<<dim3(SEQ / QT, B_SZ * NHEAD), 256, ATTN_SMEM>>>(q, k, v, ao);

    gemm_bias_kernel<<<ggrid, 256>>>(ao, Wo, bo, out, M, D_MODEL, D_MODEL);
}

// round 3
// speedup vs baseline: 1.7087x; 1.1412x over previous
#include <cuda_runtime.h>
#include <math.h>
#include <stdint.h>

#define NHEAD   8
#define HD      64
#define D_MODEL 512
#define B_SZ    2
#define SEQ     4096
#define MTOT    (B_SZ*SEQ)

// Scratch (allocation-free rule: __device__ globals)
__device__ unsigned g_qh[MTOT*D_MODEL];
__device__ unsigned g_ql[MTOT*D_MODEL];
__device__ unsigned g_kh[MTOT*D_MODEL];
__device__ unsigned g_kl[MTOT*D_MODEL];
__device__ float    g_v [MTOT*D_MODEL];
__device__ float    g_ao[MTOT*D_MODEL];

// ---------------------------------------------------------------------------
// GEMM: C[M,N] = A[M,K] @ W[K,N] + bias[N]  (fp32, FFMA path)
// ---------------------------------------------------------------------------
__global__ __launch_bounds__(256) void gemm_bias_kernel(
    const float* __restrict__ A, const float* __restrict__ W,
    const float* __restrict__ bias, float* __restrict__ C,
    int M, int N, int K)
{
    __shared__ float As[8][128];
    __shared__ float Bs[8][128];

    const int tid  = threadIdx.x;
    const int tx   = tid & 15;
    const int ty   = tid >> 4;
    const int row0 = blockIdx.y * 128;
    const int col0 = blockIdx.x * 128;

    float acc[8][8];
#pragma unroll
    for (int i = 0; i < 8; i++)
#pragma unroll
        for (int j = 0; j < 8; j++) acc[i][j] = 0.f;

    const int ar = tid >> 1;
    const int ak = (tid & 1) << 2;
    const int bk = tid >> 5;
    const int bc = (tid & 31) << 2;

    for (int k0 = 0; k0 < K; k0 += 8) {
        float4 av = *(const float4*)(A + (size_t)(row0 + ar) * K + k0 + ak);
        As[ak + 0][ar] = av.x;
        As[ak + 1][ar] = av.y;
        As[ak + 2][ar] = av.z;
        As[ak + 3][ar] = av.w;
        *(float4*)&Bs[bk][bc] =
            *(const float4*)(W + (size_t)(k0 + bk) * N + col0 + bc);
        __syncthreads();

#pragma unroll
        for (int kk = 0; kk < 8; kk++) {
            float a[8], b[8];
            *(float4*)&a[0] = *(const float4*)&As[kk][ty * 8];
            *(float4*)&a[4] = *(const float4*)&As[kk][ty * 8 + 4];
            *(float4*)&b[0] = *(const float4*)&Bs[kk][tx * 8];
            *(float4*)&b[4] = *(const float4*)&Bs[kk][tx * 8 + 4];
#pragma unroll
            for (int i = 0; i < 8; i++)
#pragma unroll
                for (int j = 0; j < 8; j++)
                    acc[i][j] += a[i] * b[j];
        }
        __syncthreads();
    }

#pragma unroll
    for (int i = 0; i < 8; i++) {
        float* crow = C + (size_t)(row0 + ty * 8 + i) * N + col0 + tx * 8;
#pragma unroll
        for (int j0 = 0; j0 < 8; j0 += 4) {
            float4 o;
            o.x = acc[i][j0 + 0] + bias[col0 + tx * 8 + j0 + 0];
            o.y = acc[i][j0 + 1] + bias[col0 + tx * 8 + j0 + 1];
            o.z = acc[i][j0 + 2] + bias[col0 + tx * 8 + j0 + 2];
            o.w = acc[i][j0 + 3] + bias[col0 + tx * 8 + j0 + 3];
            *(float4*)(crow + j0) = o;
        }
    }
}

// ---------------------------------------------------------------------------
// Same GEMM, but epilogue writes split-TF32 (hi = bit-truncated, lo = exact
// fp32 residual), with a scale folded in (exact for powers of 2).
// ---------------------------------------------------------------------------
__global__ __launch_bounds__(256) void gemm_bias_split_kernel(
    const float* __restrict__ A, const float* __restrict__ W,
    const float* __restrict__ bias, unsigned* __restrict__ Chi,
    unsigned* __restrict__ Clo, int M, int N, int K, float scale)
{
    __shared__ float As[8][128];
    __shared__ float Bs[8][128];

    const int tid  = threadIdx.x;
    const int tx   = tid & 15;
    const int ty   = tid >> 4;
    const int row0 = blockIdx.y * 128;
    const int col0 = blockIdx.x * 128;

    float acc[8][8];
#pragma unroll
    for (int i = 0; i < 8; i++)
#pragma unroll
        for (int j = 0; j < 8; j++) acc[i][j] = 0.f;

    const int ar = tid >> 1;
    const int ak = (tid & 1) << 2;
    const int bk = tid >> 5;
    const int bc = (tid & 31) << 2;

    for (int k0 = 0; k0 < K; k0 += 8) {
        float4 av = *(const float4*)(A + (size_t)(row0 + ar) * K + k0 + ak);
        As[ak + 0][ar] = av.x;
        As[ak + 1][ar] = av.y;
        As[ak + 2][ar] = av.z;
        As[ak + 3][ar] = av.w;
        *(float4*)&Bs[bk][bc] =
            *(const float4*)(W + (size_t)(k0 + bk) * N + col0 + bc);
        __syncthreads();

#pragma unroll
        for (int kk = 0; kk < 8; kk++) {
            float a[8], b[8];
            *(float4*)&a[0] = *(const float4*)&As[kk][ty * 8];
            *(float4*)&a[4] = *(const float4*)&As[kk][ty * 8 + 4];
            *(float4*)&b[0] = *(const float4*)&Bs[kk][tx * 8];
            *(float4*)&b[4] = *(const float4*)&Bs[kk][tx * 8 + 4];
#pragma unroll
            for (int i = 0; i < 8; i++)
#pragma unroll
                for (int j = 0; j < 8; j++)
                    acc[i][j] += a[i] * b[j];
        }
        __syncthreads();
    }

#pragma unroll
    for (int i = 0; i < 8; i++) {
        size_t ro = (size_t)(row0 + ty * 8 + i) * N + col0 + tx * 8;
#pragma unroll
        for (int j0 = 0; j0 < 8; j0 += 4) {
            uint4 hv, lv;
#pragma unroll
            for (int u = 0; u < 4; u++) {
                float w = (acc[i][j0 + u] + bias[col0 + tx * 8 + j0 + u]) * scale;
                unsigned hb = __float_as_uint(w) & 0xFFFFE000u;
                float lo = w - __uint_as_float(hb);
                ((unsigned*)&hv)[u] = hb;
                ((unsigned*)&lv)[u] = __float_as_uint(lo);
            }
            *(uint4*)(Chi + ro + j0) = hv;
            *(uint4*)(Clo + ro + j0) = lv;
        }
    }
}

// ---------------------------------------------------------------------------
// Flash attention v3: TF32 mma.sync, pre-split inputs, cp.async double buffer,
// shuffle-based P transpose. Block = 8 warps = 128 query rows.
// ---------------------------------------------------------------------------
#define QT   128
#define KT   64
#define KSS  68
#define VSS  72
#define STG  (KT*KSS*2 + KT*VSS)     // 13312 words per stage buffer
#define ATTN_SMEM (2*STG*4)          // 106496 bytes

__device__ __forceinline__ void cp16(uint32_t dst, const void* src) {
    asm volatile("cp.async.cg.shared.global [%0], [%1], 16;\n"
                 :: "r"(dst), "l"(src));
}

__device__ __forceinline__ void mma8(float* c, const uint32_t* a,
                                     uint32_t b0, uint32_t b1) {
    asm volatile(
        "mma.sync.aligned.m16n8k8.row.col.f32.tf32.tf32.f32 "
        "{%0,%1,%2,%3}, {%4,%5,%6,%7}, {%8,%9}, {%0,%1,%2,%3};\n"
        : "+f"(c[0]), "+f"(c[1]), "+f"(c[2]), "+f"(c[3])
        : "r"(a[0]), "r"(a[1]), "r"(a[2]), "r"(a[3]), "r"(b0), "r"(b1));
}

__global__ __launch_bounds__(256) void attn_kernel(
    const unsigned* __restrict__ Qh, const unsigned* __restrict__ Ql,
    const unsigned* __restrict__ Khg, const unsigned* __restrict__ Klg,
    const float* __restrict__ Vg, float* __restrict__ O)
{
    extern __shared__ uint32_t sm[];

    const int tid  = threadIdx.x;
    const int lane = tid & 31;
    const int warp = tid >> 5;
    const int g    = lane >> 2;
    const int t    = lane & 3;

    const int bh = blockIdx.y;
    const int b  = bh >> 3;
    const int h  = bh & 7;
    const int q0 = blockIdx.x * QT;

    const size_t base = (size_t)b * SEQ * D_MODEL + h * HD;
    const unsigned* Qhb = Qh  + base;
    const unsigned* Qlb = Ql  + base;
    const unsigned* Khb = Khg + base;
    const unsigned* Klb = Klg + base;
    const float*    Vb  = Vg  + base;

    // --- stage Q hi/lo into smem (transient; overlaps stage buffers) ---
    for (int i = tid; i < QT * 16; i += 256) {
        int r = i >> 4;
        int c = (i & 15) * 4;
        *(uint4*)&sm[r * KSS + c] =
            *(const uint4*)(Qhb + (size_t)(q0 + r) * D_MODEL + c);
        *(uint4*)&sm[QT * KSS + r * KSS + c] =
            *(const uint4*)(Qlb + (size_t)(q0 + r) * D_MODEL + c);
    }
    __syncthreads();

    // --- Q fragments to registers ---
    uint32_t qh[8][4], ql[8][4];
    const int rb = warp * 16 + g;
#pragma unroll
    for (int s = 0; s < 8; s++) {
        qh[s][0] = sm[rb * KSS + 8 * s + t];
        qh[s][1] = sm[(rb + 8) * KSS + 8 * s + t];
        qh[s][2] = sm[rb * KSS + 8 * s + t + 4];
        qh[s][3] = sm[(rb + 8) * KSS + 8 * s + t + 4];
        ql[s][0] = sm[QT * KSS + rb * KSS + 8 * s + t];
        ql[s][1] = sm[QT * KSS + (rb + 8) * KSS + 8 * s + t];
        ql[s][2] = sm[QT * KSS + rb * KSS + 8 * s + t + 4];
        ql[s][3] = sm[QT * KSS + (rb + 8) * KSS + 8 * s + t + 4];
    }
    __syncthreads();

    // --- cp.async staging: 64 rows x 4 threads/row, 4 chunks each per array ---
    const int sr = tid >> 2;
    const int sc0 = (tid & 3) * 16;

#define STAGE(bufi, kt)                                                        \
    do {                                                                       \
        uint32_t* dptr = sm + (bufi) * STG;                                    \
        size_t gro = (size_t)((kt) + sr) * D_MODEL;                            \
        uint32_t aKh = (uint32_t)__cvta_generic_to_shared(dptr + sr * KSS);    \
        uint32_t aKl = (uint32_t)__cvta_generic_to_shared(dptr + KT*KSS + sr*KSS); \
        uint32_t aV  = (uint32_t)__cvta_generic_to_shared(dptr + 2*KT*KSS + sr*VSS); \
        _Pragma("unroll")                                                      \
        for (int u = 0; u < 4; u++) {                                          \
            int c = sc0 + u * 4;                                               \
            cp16(aKh + c * 4, Khb + gro + c);                                  \
            cp16(aKl + c * 4, Klb + gro + c);                                  \
            cp16(aV  + c * 4, Vb  + gro + c);                                  \
        }                                                                      \
        asm volatile("cp.async.commit_group;\n");                              \
    } while (0)

    float o[8][4];
#pragma unroll
    for (int j = 0; j < 8; j++)
#pragma unroll
        for (int k4 = 0; k4 < 4; k4++) o[j][k4] = 0.f;
    float m0 = -1e30f, m1 = -1e30f, l0s = 0.f, l1s = 0.f;

    STAGE(0, 0);

    const int NT = SEQ / KT;
    for (int it = 0; it < NT; it++) {
        if (it + 1 < NT) {
            STAGE((it + 1) & 1, (it + 1) * KT);
            asm volatile("cp.async.wait_group 1;\n");
        } else {
            asm volatile("cp.async.wait_group 0;\n");
        }
        __syncthreads();

        const uint32_t* Khs = sm + (it & 1) * STG;
        const uint32_t* Kls = Khs + KT * KSS;
        const uint32_t* Vts = Khs + 2 * KT * KSS;

        // --- S = Q K^T (3-term split TF32) ---
        float sf[8][4];
#pragma unroll
        for (int j = 0; j < 8; j++)
#pragma unroll
            for (int k4 = 0; k4 < 4; k4++) sf[j][k4] = 0.f;

#pragma unroll
        for (int s = 0; s < 8; s++) {
#pragma unroll
            for (int j = 0; j < 8; j++) {
                int ko = (8 * j + g) * KSS + 8 * s + t;
                uint32_t bh0 = Khs[ko], bh1 = Khs[ko + 4];
                uint32_t bl0 = Kls[ko], bl1 = Kls[ko + 4];
                mma8(sf[j], qh[s], bh0, bh1);
                mma8(sf[j], qh[s], bl0, bl1);
                mma8(sf[j], ql[s], bh0, bh1);
            }
        }

        // --- online softmax (scale already folded into Q) ---
        float rm0 = -1e30f, rm1 = -1e30f;
#pragma unroll
        for (int j = 0; j < 8; j++) {
            rm0 = fmaxf(rm0, fmaxf(sf[j][0], sf[j][1]));
            rm1 = fmaxf(rm1, fmaxf(sf[j][2], sf[j][3]));
        }
        rm0 = fmaxf(rm0, __shfl_xor_sync(0xffffffffu, rm0, 1));
        rm0 = fmaxf(rm0, __shfl_xor_sync(0xffffffffu, rm0, 2));
        rm1 = fmaxf(rm1, __shfl_xor_sync(0xffffffffu, rm1, 1));
        rm1 = fmaxf(rm1, __shfl_xor_sync(0xffffffffu, rm1, 2));

        float nm0 = fmaxf(m0, rm0), nm1 = fmaxf(m1, rm1);
        float f0 = __expf(m0 - nm0), f1 = __expf(m1 - nm1);

        float rs0 = 0.f, rs1 = 0.f;
#pragma unroll
        for (int j = 0; j < 8; j++) {
            // exp, then truncate to tf32 bits BEFORE summing so numerator
            // (MMA) and denominator (l) stay consistent.
            float p0 = __uint_as_float(
                __float_as_uint(__expf(sf[j][0] - nm0)) & 0xFFFFE000u);
            float p1 = __uint_as_float(
                __float_as_uint(__expf(sf[j][1] - nm0)) & 0xFFFFE000u);
            float p2 = __uint_as_float(
                __float_as_uint(__expf(sf[j][2] - nm1)) & 0xFFFFE000u);
            float p3 = __uint_as_float(
                __float_as_uint(__expf(sf[j][3] - nm1)) & 0xFFFFE000u);
            rs0 += p0 + p1;
            rs1 += p2 + p3;
            sf[j][0] = p0; sf[j][1] = p1; sf[j][2] = p2; sf[j][3] = p3;
        }
        rs0 += __shfl_xor_sync(0xffffffffu, rs0, 1);
        rs0 += __shfl_xor_sync(0xffffffffu, rs0, 2);
        rs1 += __shfl_xor_sync(0xffffffffu, rs1, 1);
        rs1 += __shfl_xor_sync(0xffffffffu, rs1, 2);

        l0s = l0s * f0 + rs0;
        l1s = l1s * f1 + rs1;
        m0 = nm0; m1 = nm1;
#pragma unroll
        for (int j = 0; j < 8; j++) {
            o[j][0] *= f0; o[j][1] *= f0;
            o[j][2] *= f1; o[j][3] *= f1;
        }

        // --- O += P V, P transposed C->A layout via shuffles ---
        const int srcLo = (lane & ~3) | (t >> 1);
        const int srcHi = srcLo + 2;
        const bool odd = (t & 1);
#pragma unroll
        for (int j = 0; j < 8; j++) {
            float x0 = __shfl_sync(0xffffffffu, sf[j][0], srcLo);
            float x1 = __shfl_sync(0xffffffffu, sf[j][1], srcLo);
            float x2 = __shfl_sync(0xffffffffu, sf[j][2], srcLo);
            float x3 = __shfl_sync(0xffffffffu, sf[j][3], srcLo);
            float y0 = __shfl_sync(0xffffffffu, sf[j][0], srcHi);
            float y1 = __shfl_sync(0xffffffffu, sf[j][1], srcHi);
            float y2 = __shfl_sync(0xffffffffu, sf[j][2], srcHi);
            float y3 = __shfl_sync(0xffffffffu, sf[j][3], srcHi);
            uint32_t a[4];
            a[0] = __float_as_uint(odd ? x1 : x0);
            a[1] = __float_as_uint(odd ? x3 : x2);
            a[2] = __float_as_uint(odd ? y1 : y0);
            a[3] = __float_as_uint(odd ? y3 : y2);
#pragma unroll
            for (int jj = 0; jj < 8; jj++) {
                int vo = (8 * j + t) * VSS + 8 * jj + g;
                mma8(o[jj], a, Vts[vo], Vts[vo + 4 * VSS]);
            }
        }
        __syncthreads();
    }

    // --- normalize + write ---
    float i0 = 1.f / l0s, i1 = 1.f / l1s;
    float* Ob = O + base;
    const int r0 = q0 + warp * 16 + g;
    const int r1 = r0 + 8;
#pragma unroll
    for (int j = 0; j < 8; j++) {
        int d = 8 * j + 2 * t;
        *(float2*)(Ob + (size_t)r0 * D_MODEL + d) =
            make_float2(o[j][0] * i0, o[j][1] * i0);
        *(float2*)(Ob + (size_t)r1 * D_MODEL + d) =
            make_float2(o[j][2] * i1, o[j][3] * i1);
    }
}

// ---------------------------------------------------------------------------
extern "C" void kernel_launch(void* const* d_in, const int* in_sizes, int n_in,
                              void* d_out, int out_size)
{
    const float* x  = (const float*)d_in[0];
    const float* Wq = (const float*)d_in[1];
    const float* bq = (const float*)d_in[2];
    const float* Wk = (const float*)d_in[3];
    const float* bk = (const float*)d_in[4];
    const float* Wv = (const float*)d_in[5];
    const float* bv = (const float*)d_in[6];
    const float* Wo = (const float*)d_in[7];
    const float* bo = (const float*)d_in[8];
    float* out = (float*)d_out;

    unsigned *qh, *ql, *kh, *kl;
    float *v, *ao;
    cudaGetSymbolAddress((void**)&qh, g_qh);
    cudaGetSymbolAddress((void**)&ql, g_ql);
    cudaGetSymbolAddress((void**)&kh, g_kh);
    cudaGetSymbolAddress((void**)&kl, g_kl);
    cudaGetSymbolAddress((void**)&v,  g_v);
    cudaGetSymbolAddress((void**)&ao, g_ao);

    cudaFuncSetAttribute(attn_kernel,
                         cudaFuncAttributeMaxDynamicSharedMemorySize, ATTN_SMEM);

    const int M = B_SZ * SEQ;
    dim3 ggrid(D_MODEL / 128, M / 128);

    gemm_bias_split_kernel<<<ggrid, 256>>>(x, Wq, bq, qh, ql,
                                           M, D_MODEL, D_MODEL, 0.125f);
    gemm_bias_split_kernel<<<ggrid, 256>>>(x, Wk, bk, kh, kl,
                                           M, D_MODEL, D_MODEL, 1.0f);
    gemm_bias_kernel<<<ggrid, 256>>>(x, Wv, bv, v, M, D_MODEL, D_MODEL);

    attn_kernel<<<dim3(SEQ / QT, B_SZ * NHEAD), 256, ATTN_SMEM>>>(
        qh, ql, kh, kl, v, ao);

    gemm_bias_kernel<<<ggrid, 256>>>(ao, Wo, bo, out, M, D_MODEL, D_MODEL);
}

// round 4
// speedup vs baseline: 2.7956x; 1.6361x over previous
#include <cuda_runtime.h>
#include <cuda_bf16.h>
#include <math.h>
#include <stdint.h>

#define NHEAD   8
#define HD      64
#define D_MODEL 512
#define B_SZ    2
#define SEQ     4096
#define MTOT    (B_SZ*SEQ)
#define KW      (D_MODEL/2)   // packed bf16-pair words per row

// ---- scratch (__device__ globals; no allocs allowed) ----
__device__ uint32_t g_xh [MTOT*KW];
__device__ uint32_t g_xl [MTOT*KW];
__device__ uint32_t g_qh [MTOT*KW];
__device__ uint32_t g_ql [MTOT*KW];
__device__ uint32_t g_kh [MTOT*KW];
__device__ uint32_t g_kl [MTOT*KW];
__device__ float    g_v  [MTOT*D_MODEL];
__device__ uint32_t g_aoh[MTOT*KW];
__device__ uint32_t g_aol[MTOT*KW];
__device__ uint32_t g_wth[4*D_MODEL*KW];   // W^T split hi, per gemm
__device__ uint32_t g_wtl[4*D_MODEL*KW];   // W^T split lo

// ---- helpers ----
__device__ __forceinline__ void split2(float a, float b,
                                       uint32_t& hi, uint32_t& lo) {
    __nv_bfloat162 h = __floats2bfloat162_rn(a, b);
    float ra = a - __bfloat162float(h.x);
    float rb = b - __bfloat162float(h.y);
    __nv_bfloat162 l = __floats2bfloat162_rn(ra, rb);
    hi = *reinterpret_cast<uint32_t*>(&h);
    lo = *reinterpret_cast<uint32_t*>(&l);
}

__device__ __forceinline__ void cp16(uint32_t dst, const void* src) {
    asm volatile("cp.async.cg.shared.global [%0], [%1], 16;\n"
                 :: "r"(dst), "l"(src));
}

// tf32 m16n8k8
__device__ __forceinline__ void mma8(float* c, const uint32_t* a,
                                     uint32_t b0, uint32_t b1) {
    asm volatile(
        "mma.sync.aligned.m16n8k8.row.col.f32.tf32.tf32.f32 "
        "{%0,%1,%2,%3}, {%4,%5,%6,%7}, {%8,%9}, {%0,%1,%2,%3};\n"
        : "+f"(c[0]), "+f"(c[1]), "+f"(c[2]), "+f"(c[3])
        : "r"(a[0]), "r"(a[1]), "r"(a[2]), "r"(a[3]), "r"(b0), "r"(b1));
}

// bf16 m16n8k16
__device__ __forceinline__ void mma16(float* c, const uint32_t* a,
                                      uint32_t b0, uint32_t b1) {
    asm volatile(
        "mma.sync.aligned.m16n8k16.row.col.f32.bf16.bf16.f32 "
        "{%0,%1,%2,%3}, {%4,%5,%6,%7}, {%8,%9}, {%0,%1,%2,%3};\n"
        : "+f"(c[0]), "+f"(c[1]), "+f"(c[2]), "+f"(c[3])
        : "r"(a[0]), "r"(a[1]), "r"(a[2]), "r"(a[3]), "r"(b0), "r"(b1));
}

// ---------------------------------------------------------------------------
// split_rows: fp32 [M][512] -> packed bf16 hi/lo [M][256]
// ---------------------------------------------------------------------------
__global__ __launch_bounds__(256) void split_rows_kernel(
    const float* __restrict__ X, uint32_t* __restrict__ Xh,
    uint32_t* __restrict__ Xl, int nwords)
{
    int i = blockIdx.x * 256 + threadIdx.x;
    if (i >= nwords) return;
    float2 v = ((const float2*)X)[i];
    uint32_t hi, lo;
    split2(v.x, v.y, hi, lo);
    Xh[i] = hi;
    Xl[i] = lo;
}

// ---------------------------------------------------------------------------
// split_T: W [K][N] fp32 -> W^T packed [N][K/2] hi/lo
// ---------------------------------------------------------------------------
__global__ __launch_bounds__(256) void split_T_kernel(
    const float* __restrict__ W, uint32_t* __restrict__ WhT,
    uint32_t* __restrict__ WlT)
{
    int idx = blockIdx.x * 256 + threadIdx.x;          // 512*256 total
    int n  = idx & (D_MODEL - 1);
    int kw = idx >> 9;
    float f0 = W[(2 * kw)     * D_MODEL + n];
    float f1 = W[(2 * kw + 1) * D_MODEL + n];
    uint32_t hi, lo;
    split2(f0, f1, hi, lo);
    WhT[n * KW + kw] = hi;
    WlT[n * KW + kw] = lo;
}

// ---------------------------------------------------------------------------
// Split-bf16 tensor GEMM: C[M,N] = A[M,K] @ W[K,N] + bias (3-term hh+hl+lh).
// A: packed hi/lo [M][K/2], B: W^T packed [N][K/2].
// Block 128x128, 8 warps m32 x n64, KTILE=32, cp.async double buffer.
// mode 0: fp32 C out.  mode 1: packed bf16 hi/lo out with scale folded.
// ---------------------------------------------------------------------------
#define GST   20                 // smem row stride (16 words + 4 pad)
#define GARR  (128*GST)          // 2560 words per array
#define GSTG  (4*GARR)           // 10240 words per stage
#define GEMM_SMEM (2*GSTG*4)     // 81920 bytes

__global__ __launch_bounds__(256) void gemm_bf16_kernel(
    const uint32_t* __restrict__ Ah, const uint32_t* __restrict__ Al,
    const uint32_t* __restrict__ Bh, const uint32_t* __restrict__ Bl,
    const float* __restrict__ bias,
    float* __restrict__ C, uint32_t* __restrict__ Chi,
    uint32_t* __restrict__ Clo, int M, int N, float scale, int mode)
{
    extern __shared__ uint32_t gs[];

    const int tid  = threadIdx.x;
    const int lane = tid & 31;
    const int warp = tid >> 5;
    const int g    = lane >> 2;
    const int t    = lane & 3;
    const int wm   = warp >> 1;
    const int wn   = warp & 1;
    const int m0   = wm * 32;
    const int nb0  = wn * 64;
    const int row0 = blockIdx.y * 128;
    const int col0 = blockIdx.x * 128;
    const int Nw   = N >> 1;

    const int r  = tid >> 1;
    const int hf = tid & 1;

#define GSTAGE(bufi, kt)                                                     \
    do {                                                                     \
        uint32_t* dp = gs + (bufi) * GSTG;                                   \
        int kw0 = (kt) * 16;                                                 \
        const uint32_t* Ahg = Ah + (size_t)(row0 + r) * KW + kw0;            \
        const uint32_t* Alg = Al + (size_t)(row0 + r) * KW + kw0;            \
        const uint32_t* Bhg = Bh + (size_t)(col0 + r) * KW + kw0;            \
        const uint32_t* Blg = Bl + (size_t)(col0 + r) * KW + kw0;            \
        uint32_t aA = (uint32_t)__cvta_generic_to_shared(dp + r * GST);      \
        uint32_t aB = (uint32_t)__cvta_generic_to_shared(dp + 2*GARR + r*GST);\
        _Pragma("unroll")                                                    \
        for (int u = 0; u < 2; u++) {                                        \
            int c = hf * 8 + u * 4;                                          \
            cp16(aA + c * 4,            Ahg + c);                            \
            cp16(aA + GARR * 4 + c * 4, Alg + c);                            \
            cp16(aB + c * 4,            Bhg + c);                            \
            cp16(aB + GARR * 4 + c * 4, Blg + c);                            \
        }                                                                    \
        asm volatile("cp.async.commit_group;\n");                            \
    } while (0)

    float acc[2][8][4];
#pragma unroll
    for (int mi = 0; mi < 2; mi++)
#pragma unroll
        for (int jn = 0; jn < 8; jn++)
#pragma unroll
            for (int u = 0; u < 4; u++) acc[mi][jn][u] = 0.f;

    GSTAGE(0, 0);
    const int NTK = D_MODEL / 32;   // 16
    for (int kt = 0; kt < NTK; kt++) {
        if (kt + 1 < NTK) {
            GSTAGE((kt + 1) & 1, kt + 1);
            asm volatile("cp.async.wait_group 1;\n");
        } else {
            asm volatile("cp.async.wait_group 0;\n");
        }
        __syncthreads();

        const uint32_t* Ahs = gs + (kt & 1) * GSTG;
        const uint32_t* Als = Ahs + GARR;
        const uint32_t* Bhs = Ahs + 2 * GARR;
        const uint32_t* Bls = Ahs + 3 * GARR;

#pragma unroll
        for (int s = 0; s < 2; s++) {
            uint32_t ah[2][4], al[2][4];
#pragma unroll
            for (int mi = 0; mi < 2; mi++) {
                int off = (m0 + 16 * mi + g) * GST + 8 * s + t;
                ah[mi][0] = Ahs[off];
                ah[mi][1] = Ahs[off + 8 * GST];
                ah[mi][2] = Ahs[off + 4];
                ah[mi][3] = Ahs[off + 8 * GST + 4];
                al[mi][0] = Als[off];
                al[mi][1] = Als[off + 8 * GST];
                al[mi][2] = Als[off + 4];
                al[mi][3] = Als[off + 8 * GST + 4];
            }
#pragma unroll
            for (int jn = 0; jn < 8; jn++) {
                int bo = (nb0 + 8 * jn + g) * GST + 8 * s + t;
                uint32_t bh0 = Bhs[bo], bh1 = Bhs[bo + 4];
                uint32_t bl0 = Bls[bo], bl1 = Bls[bo + 4];
#pragma unroll
                for (int mi = 0; mi < 2; mi++) {
                    mma16(acc[mi][jn], ah[mi], bh0, bh1);
                    mma16(acc[mi][jn], ah[mi], bl0, bl1);
                    mma16(acc[mi][jn], al[mi], bh0, bh1);
                }
            }
        }
        __syncthreads();
    }

    // epilogue
#pragma unroll
    for (int mi = 0; mi < 2; mi++) {
        int r0 = row0 + m0 + 16 * mi + g;
        int r1 = r0 + 8;
#pragma unroll
        for (int jn = 0; jn < 8; jn++) {
            int n0e = col0 + nb0 + 8 * jn + 2 * t;
            float b0v = bias[n0e], b1v = bias[n0e + 1];
            float v00 = acc[mi][jn][0] + b0v;
            float v01 = acc[mi][jn][1] + b1v;
            float v10 = acc[mi][jn][2] + b0v;
            float v11 = acc[mi][jn][3] + b1v;
            if (mode == 0) {
                *(float2*)(C + (size_t)r0 * N + n0e) = make_float2(v00, v01);
                *(float2*)(C + (size_t)r1 * N + n0e) = make_float2(v10, v11);
            } else {
                int wi = n0e >> 1;
                uint32_t hi, lo;
                split2(v00 * scale, v01 * scale, hi, lo);
                Chi[(size_t)r0 * Nw + wi] = hi;
                Clo[(size_t)r0 * Nw + wi] = lo;
                split2(v10 * scale, v11 * scale, hi, lo);
                Chi[(size_t)r1 * Nw + wi] = hi;
                Clo[(size_t)r1 * Nw + wi] = lo;
            }
        }
    }
}

// ---------------------------------------------------------------------------
// Flash attention v4: QK^T = 2-term bf16 split (m16n8k16), PV = tf32.
// Q/K pre-split packed; cp.async double buffer; shuffle P transpose.
// Output written directly as packed bf16 hi/lo for the O projection.
// ---------------------------------------------------------------------------
#define QT   128
#define KT   64
#define KSS  36                          // 32 words + 4 pad
#define VSS  72
#define SKL  (KT*KSS)                    // 2304
#define SV   (2*KT*KSS)                  // 4608
#define STG  (2*KT*KSS + KT*VSS)         // 9216 words / stage
#define ATTN_SMEM (2*STG*4)              // 73728 bytes

__global__ __launch_bounds__(256) void attn_kernel(
    const uint32_t* __restrict__ Qh, const uint32_t* __restrict__ Ql,
    const uint32_t* __restrict__ Khg, const uint32_t* __restrict__ Klg,
    const float* __restrict__ Vg,
    uint32_t* __restrict__ AOh, uint32_t* __restrict__ AOl)
{
    extern __shared__ uint32_t sm[];

    const int tid  = threadIdx.x;
    const int lane = tid & 31;
    const int warp = tid >> 5;
    const int g    = lane >> 2;
    const int t    = lane & 3;

    const int bh = blockIdx.y;
    const int b  = bh >> 3;
    const int h  = bh & 7;
    const int q0 = blockIdx.x * QT;

    const size_t baseW = (size_t)b * SEQ * KW + h * (HD / 2);
    const size_t baseF = (size_t)b * SEQ * D_MODEL + h * HD;
    const uint32_t* Qhb = Qh  + baseW;
    const uint32_t* Qlb = Ql  + baseW;
    const uint32_t* Khb = Khg + baseW;
    const uint32_t* Klb = Klg + baseW;
    const float*    Vb  = Vg  + baseF;

    // --- stage Q hi/lo into smem (transient, inside stage-0 region) ---
    for (int i = tid; i < QT * 8; i += 256) {
        int r = i >> 3;
        int c = (i & 7) * 4;
        *(uint4*)&sm[r * KSS + c] =
            *(const uint4*)(Qhb + (size_t)(q0 + r) * KW + c);
        *(uint4*)&sm[QT * KSS + r * KSS + c] =
            *(const uint4*)(Qlb + (size_t)(q0 + r) * KW + c);
    }
    __syncthreads();

    // --- Q fragments (bf16 m16n8k16 A layout), s = k16 group 0..3 ---
    uint32_t qh[4][4], ql[4][4];
    const int rb = warp * 16 + g;
#pragma unroll
    for (int s = 0; s < 4; s++) {
        qh[s][0] = sm[rb * KSS + 8 * s + t];
        qh[s][1] = sm[(rb + 8) * KSS + 8 * s + t];
        qh[s][2] = sm[rb * KSS + 8 * s + t + 4];
        qh[s][3] = sm[(rb + 8) * KSS + 8 * s + t + 4];
        ql[s][0] = sm[QT * KSS + rb * KSS + 8 * s + t];
        ql[s][1] = sm[QT * KSS + (rb + 8) * KSS + 8 * s + t];
        ql[s][2] = sm[QT * KSS + rb * KSS + 8 * s + t + 4];
        ql[s][3] = sm[QT * KSS + (rb + 8) * KSS + 8 * s + t + 4];
    }
    __syncthreads();

    const int sr = tid >> 2;
    const int sq = tid & 3;

#define STAGE(bufi, kt)                                                       \
    do {                                                                      \
        uint32_t* dp = sm + (bufi) * STG;                                     \
        size_t grK = (size_t)((kt) + sr) * KW;                                \
        size_t grV = (size_t)((kt) + sr) * D_MODEL;                           \
        uint32_t aKh = (uint32_t)__cvta_generic_to_shared(dp + sr * KSS);     \
        uint32_t aKl = (uint32_t)__cvta_generic_to_shared(dp + SKL + sr*KSS); \
        uint32_t aV  = (uint32_t)__cvta_generic_to_shared(dp + SV + sr*VSS);  \
        _Pragma("unroll")                                                     \
        for (int u = 0; u < 2; u++) {                                         \
            int c = sq * 8 + u * 4;                                           \
            cp16(aKh + c * 4, Khb + grK + c);                                 \
            cp16(aKl + c * 4, Klb + grK + c);                                 \
        }                                                                     \
        _Pragma("unroll")                                                     \
        for (int u = 0; u < 4; u++) {                                         \
            int c = sq * 16 + u * 4;                                          \
            cp16(aV + c * 4, Vb + grV + c);                                   \
        }                                                                     \
        asm volatile("cp.async.commit_group;\n");                             \
    } while (0)

    float o[8][4];
#pragma unroll
    for (int j = 0; j < 8; j++)
#pragma unroll
        for (int u = 0; u < 4; u++) o[j][u] = 0.f;
    float m0 = -1e30f, m1 = -1e30f, l0s = 0.f, l1s = 0.f;

    STAGE(0, 0);

    const int NT = SEQ / KT;
    for (int it = 0; it < NT; it++) {
        if (it + 1 < NT) {
            STAGE((it + 1) & 1, (it + 1) * KT);
            asm volatile("cp.async.wait_group 1;\n");
        } else {
            asm volatile("cp.async.wait_group 0;\n");
        }
        __syncthreads();

        const uint32_t* Khs = sm + (it & 1) * STG;
        const uint32_t* Kls = Khs + SKL;
        const uint32_t* Vts = Khs + SV;

        // --- S = Q K^T : hh + hl + lh, bf16 m16n8k16 ---
        float sf[8][4];
#pragma unroll
        for (int j = 0; j < 8; j++)
#pragma unroll
            for (int u = 0; u < 4; u++) sf[j][u] = 0.f;

#pragma unroll
        for (int s = 0; s < 4; s++) {
#pragma unroll
            for (int j = 0; j < 8; j++) {
                int ko = (8 * j + g) * KSS + 8 * s + t;
                uint32_t bh0 = Khs[ko], bh1 = Khs[ko + 4];
                uint32_t bl0 = Kls[ko], bl1 = Kls[ko + 4];
                mma16(sf[j], qh[s], bh0, bh1);
                mma16(sf[j], qh[s], bl0, bl1);
                mma16(sf[j], ql[s], bh0, bh1);
            }
        }

        // --- online softmax (1/8 scale folded into Q at split time) ---
        float rm0 = -1e30f, rm1 = -1e30f;
#pragma unroll
        for (int j = 0; j < 8; j++) {
            rm0 = fmaxf(rm0, fmaxf(sf[j][0], sf[j][1]));
            rm1 = fmaxf(rm1, fmaxf(sf[j][2], sf[j][3]));
        }
        rm0 = fmaxf(rm0, __shfl_xor_sync(0xffffffffu, rm0, 1));
        rm0 = fmaxf(rm0, __shfl_xor_sync(0xffffffffu, rm0, 2));
        rm1 = fmaxf(rm1, __shfl_xor_sync(0xffffffffu, rm1, 1));
        rm1 = fmaxf(rm1, __shfl_xor_sync(0xffffffffu, rm1, 2));

        float nm0 = fmaxf(m0, rm0), nm1 = fmaxf(m1, rm1);
        float f0 = __expf(m0 - nm0), f1 = __expf(m1 - nm1);

        float rs0 = 0.f, rs1 = 0.f;
#pragma unroll
        for (int j = 0; j < 8; j++) {
            float p0 = __uint_as_float(
                __float_as_uint(__expf(sf[j][0] - nm0)) & 0xFFFFE000u);
            float p1 = __uint_as_float(
                __float_as_uint(__expf(sf[j][1] - nm0)) & 0xFFFFE000u);
            float p2 = __uint_as_float(
                __float_as_uint(__expf(sf[j][2] - nm1)) & 0xFFFFE000u);
            float p3 = __uint_as_float(
                __float_as_uint(__expf(sf[j][3] - nm1)) & 0xFFFFE000u);
            rs0 += p0 + p1;
            rs1 += p2 + p3;
            sf[j][0] = p0; sf[j][1] = p1; sf[j][2] = p2; sf[j][3] = p3;
        }
        rs0 += __shfl_xor_sync(0xffffffffu, rs0, 1);
        rs0 += __shfl_xor_sync(0xffffffffu, rs0, 2);
        rs1 += __shfl_xor_sync(0xffffffffu, rs1, 1);
        rs1 += __shfl_xor_sync(0xffffffffu, rs1, 2);

        l0s = l0s * f0 + rs0;
        l1s = l1s * f1 + rs1;
        m0 = nm0; m1 = nm1;
#pragma unroll
        for (int j = 0; j < 8; j++) {
            o[j][0] *= f0; o[j][1] *= f0;
            o[j][2] *= f1; o[j][3] *= f1;
        }

        // --- O += P V (tf32), P transposed C->A layout via shuffles ---
        const int srcLo = (lane & ~3) | (t >> 1);
        const int srcHi = srcLo + 2;
        const bool odd = (t & 1);
#pragma unroll
        for (int j = 0; j < 8; j++) {
            float x0 = __shfl_sync(0xffffffffu, sf[j][0], srcLo);
            float x1 = __shfl_sync(0xffffffffu, sf[j][1], srcLo);
            float x2 = __shfl_sync(0xffffffffu, sf[j][2], srcLo);
            float x3 = __shfl_sync(0xffffffffu, sf[j][3], srcLo);
            float y0 = __shfl_sync(0xffffffffu, sf[j][0], srcHi);
            float y1 = __shfl_sync(0xffffffffu, sf[j][1], srcHi);
            float y2 = __shfl_sync(0xffffffffu, sf[j][2], srcHi);
            float y3 = __shfl_sync(0xffffffffu, sf[j][3], srcHi);
            uint32_t a[4];
            a[0] = __float_as_uint(odd ? x1 : x0);
            a[1] = __float_as_uint(odd ? x3 : x2);
            a[2] = __float_as_uint(odd ? y1 : y0);
            a[3] = __float_as_uint(odd ? y3 : y2);
#pragma unroll
            for (int jj = 0; jj < 8; jj++) {
                int vo = (8 * j + t) * VSS + 8 * jj + g;
                mma8(o[jj], a, Vts[vo], Vts[vo + 4 * VSS]);
            }
        }
        __syncthreads();
    }

    // --- normalize + write packed bf16 hi/lo (feeds O projection) ---
    float i0 = 1.f / l0s, i1 = 1.f / l1s;
    uint32_t* AOhb = AOh + baseW;
    uint32_t* AOlb = AOl + baseW;
    const int r0 = q0 + warp * 16 + g;
    const int r1 = r0 + 8;
#pragma unroll
    for (int j = 0; j < 8; j++) {
        int wi = 4 * j + t;
        uint32_t hi, lo;
        split2(o[j][0] * i0, o[j][1] * i0, hi, lo);
        AOhb[(size_t)r0 * KW + wi] = hi;
        AOlb[(size_t)r0 * KW + wi] = lo;
        split2(o[j][2] * i1, o[j][3] * i1, hi, lo);
        AOhb[(size_t)r1 * KW + wi] = hi;
        AOlb[(size_t)r1 * KW + wi] = lo;
    }
}

// ---------------------------------------------------------------------------
extern "C" void kernel_launch(void* const* d_in, const int* in_sizes, int n_in,
                              void* d_out, int out_size)
{
    const float* x  = (const float*)d_in[0];
    const float* Wq = (const float*)d_in[1];
    const float* bq = (const float*)d_in[2];
    const float* Wk = (const float*)d_in[3];
    const float* bk = (const float*)d_in[4];
    const float* Wv = (const float*)d_in[5];
    const float* bv = (const float*)d_in[6];
    const float* Wo = (const float*)d_in[7];
    const float* bo = (const float*)d_in[8];
    float* out = (float*)d_out;

    uint32_t *xh, *xl, *qh, *ql, *kh, *kl, *aoh, *aol, *wth, *wtl;
    float *v;
    cudaGetSymbolAddress((void**)&xh,  g_xh);
    cudaGetSymbolAddress((void**)&xl,  g_xl);
    cudaGetSymbolAddress((void**)&qh,  g_qh);
    cudaGetSymbolAddress((void**)&ql,  g_ql);
    cudaGetSymbolAddress((void**)&kh,  g_kh);
    cudaGetSymbolAddress((void**)&kl,  g_kl);
    cudaGetSymbolAddress((void**)&v,   g_v);
    cudaGetSymbolAddress((void**)&aoh, g_aoh);
    cudaGetSymbolAddress((void**)&aol, g_aol);
    cudaGetSymbolAddress((void**)&wth, g_wth);
    cudaGetSymbolAddress((void**)&wtl, g_wtl);

    cudaFuncSetAttribute(attn_kernel,
                         cudaFuncAttributeMaxDynamicSharedMemorySize, ATTN_SMEM);
    cudaFuncSetAttribute(gemm_bf16_kernel,
                         cudaFuncAttributeMaxDynamicSharedMemorySize, GEMM_SMEM);

    const int M = MTOT;
    const int WSZ = D_MODEL * KW;   // words per W^T array

    // split inputs
    split_rows_kernel<<<(M * KW) / 256, 256>>>(x, xh, xl, M * KW);
    split_T_kernel<<<WSZ / 256, 256>>>(Wq, wth + 0 * WSZ, wtl + 0 * WSZ);
    split_T_kernel<<<WSZ / 256, 256>>>(Wk, wth + 1 * WSZ, wtl + 1 * WSZ);
    split_T_kernel<<<WSZ / 256, 256>>>(Wv, wth + 2 * WSZ, wtl + 2 * WSZ);
    split_T_kernel<<<WSZ / 256, 256>>>(Wo, wth + 3 * WSZ, wtl + 3 * WSZ);

    dim3 ggrid(D_MODEL / 128, M / 128);
    // Q: split output, 1/8 softmax scale folded in
    gemm_bf16_kernel<<<ggrid, 256, GEMM_SMEM>>>(
        xh, xl, wth + 0 * WSZ, wtl + 0 * WSZ, bq,
        nullptr, qh, ql, M, D_MODEL, 0.125f, 1);
    // K: split output
    gemm_bf16_kernel<<<ggrid, 256, GEMM_SMEM>>>(
        xh, xl, wth + 1 * WSZ, wtl + 1 * WSZ, bk,
        nullptr, kh, kl, M, D_MODEL, 1.0f, 1);
    // V: fp32 output
    gemm_bf16_kernel<<<ggrid, 256, GEMM_SMEM>>>(
        xh, xl, wth + 2 * WSZ, wtl + 2 * WSZ, bv,
        v, nullptr, nullptr, M, D_MODEL, 1.0f, 0);

    attn_kernel<<<dim3(SEQ / QT, B_SZ * NHEAD), 256, ATTN_SMEM>>>(
        qh, ql, kh, kl, v, aoh, aol);

    // O projection: consumes attention's packed output, fp32 result
    gemm_bf16_kernel<<<ggrid, 256, GEMM_SMEM>>>(
        aoh, aol, wth + 3 * WSZ, wtl + 3 * WSZ, bo,
        out, nullptr, nullptr, M, D_MODEL, 1.0f, 0);
}